// round 1
// baseline (speedup 1.0000x reference)
#include <cuda_runtime.h>
#include <cuda_bf16.h>
#include <cstdint>

// Embedding gather: out[token, :] = embeddings[x[token], :]
// x:          int32 [4, 2048]          (in_sizes[0] = 8192)
// embeddings: fp32  [32000, 1024]      (in_sizes[1] = 32768000)
// out:        fp32  [8192, 1024]
//
// Pure memory-bound copy: ~33.5 MB gathered read + ~33.5 MB write.
// One CTA per token row; 256 threads x float4 = 4096 bytes = one full row.

#ifndef EMBED_DIM
#define EMBED_DIM 1024
#endif

__global__ __launch_bounds__(256, 8)
void embedding_gather_kernel(const int* __restrict__ x,
                             const float4* __restrict__ emb,
                             float4* __restrict__ out)
{
    const int token = blockIdx.x;
    const int row   = __ldg(&x[token]);

    // 1024 floats = 256 float4 per row
    const float4* __restrict__ src = emb + (size_t)row   * (EMBED_DIM / 4);
    float4*       __restrict__ dst = out + (size_t)token * (EMBED_DIM / 4);

    dst[threadIdx.x] = __ldg(&src[threadIdx.x]);
}

extern "C" void kernel_launch(void* const* d_in, const int* in_sizes, int n_in,
                              void* d_out, int out_size)
{
    const int*    x   = (const int*)d_in[0];
    const float4* emb = (const float4*)d_in[1];
    float4*       out = (float4*)d_out;

    const int n_tokens = in_sizes[0];   // 8192

    embedding_gather_kernel<<<n_tokens, 256>>>(x, emb, out);
}

// round 2
// speedup vs baseline: 1.0444x; 1.0444x over previous
#include <cuda_runtime.h>
#include <cuda_bf16.h>
#include <cstdint>

// Embedding gather: out[token, :] = embeddings[x[token], :]
// x:          int32 [8192]
// embeddings: fp32  [32000, 1024]
// out:        fp32  [8192, 1024]
//
// 67 MB of pure memory traffic. Strategy: high MLP — each 256-thread block
// handles TOK_PER_BLK=8 tokens; each thread issues 8 independent float4
// loads (one per token) before any store, so 8 DRAM requests are in flight
// per thread. Streaming stores (__stcs) keep the write-once output from
// polluting L2, preserving capacity for duplicated table rows.

#ifndef EMBED_DIM
#define EMBED_DIM 1024
#endif

#define TOK_PER_BLK 8
#define F4_PER_ROW (EMBED_DIM / 4)   // 256

__global__ __launch_bounds__(256, 8)
void embedding_gather_kernel(const int* __restrict__ x,
                             const float4* __restrict__ emb,
                             float4* __restrict__ out)
{
    const int tok0 = blockIdx.x * TOK_PER_BLK;
    const int t    = threadIdx.x;          // 0..255 -> column (float4 index)

    // Gather the 8 row ids (tiny, L1/L2-resident after first wave)
    int rows[TOK_PER_BLK];
#pragma unroll
    for (int i = 0; i < TOK_PER_BLK; ++i)
        rows[i] = __ldg(&x[tok0 + i]);

    // Issue all 8 independent loads back-to-back (MLP=8)
    float4 v[TOK_PER_BLK];
#pragma unroll
    for (int i = 0; i < TOK_PER_BLK; ++i)
        v[i] = __ldg(&emb[(size_t)rows[i] * F4_PER_ROW + t]);

    // Streaming stores: output is write-once, evict-first in L2
    float4* dst = out + (size_t)tok0 * F4_PER_ROW + t;
#pragma unroll
    for (int i = 0; i < TOK_PER_BLK; ++i)
        __stcs(dst + (size_t)i * F4_PER_ROW, v[i]);
}

extern "C" void kernel_launch(void* const* d_in, const int* in_sizes, int n_in,
                              void* d_out, int out_size)
{
    const int*    x   = (const int*)d_in[0];
    const float4* emb = (const float4*)d_in[1];
    float4*       out = (float4*)d_out;

    const int n_tokens = in_sizes[0];                 // 8192
    const int n_blocks = n_tokens / TOK_PER_BLK;      // 1024

    embedding_gather_kernel<<<n_blocks, 256>>>(x, emb, out);
}

// round 4
// speedup vs baseline: 1.0963x; 1.0497x over previous
#include <cuda_runtime.h>
#include <cuda_bf16.h>
#include <cstdint>

// Embedding gather: out[token, :] = embeddings[x[token], :]
// x:          int32 [8192]
// embeddings: fp32  [32000, 1024]
// out:        fp32  [8192, 1024]
//
// Latency/balance-optimized: 128-thread blocks, 4 tokens per block, each
// thread issues 8 independent float4 loads (MLP=8) before storing. Grid of
// 2048 blocks (13.8/SM) halves the wave-imbalance tail vs 1024 blocks while
// keeping full occupancy (128thr x 16 blk = 2048 thr/SM).
//
// (Re-submission of R3 candidate: previous round died to a container
// infra failure, not a kernel failure.)

#ifndef EMBED_DIM
#define EMBED_DIM 1024
#endif

#define THREADS     128
#define TOK_PER_BLK 4
#define F4_PER_ROW  (EMBED_DIM / 4)                 // 256
#define F4_PER_BLK  (TOK_PER_BLK * F4_PER_ROW)      // 1024
#define ITERS       (F4_PER_BLK / THREADS)          // 8

__global__ __launch_bounds__(THREADS, 16)
void embedding_gather_kernel(const int* __restrict__ x,
                             const float4* __restrict__ emb,
                             float4* __restrict__ out)
{
    const int tok0 = blockIdx.x * TOK_PER_BLK;
    const int t    = threadIdx.x;

    // Row ids for the 4 tokens this block serves (tiny, cache-resident)
    int rows[TOK_PER_BLK];
#pragma unroll
    for (int i = 0; i < TOK_PER_BLK; ++i)
        rows[i] = __ldg(&x[tok0 + i]);

    // Each thread covers f4 indices t, t+128, ..., t+896 within the
    // 1024-f4 block tile. idx/256 -> token, idx%256 -> column.
    // All 8 loads are independent -> MLP=8.
    float4 v[ITERS];
#pragma unroll
    for (int i = 0; i < ITERS; ++i) {
        const int idx = t + i * THREADS;
        const int tok = idx >> 8;          // idx / 256
        const int col = idx & 255;         // idx % 256
        v[i] = __ldg(&emb[(size_t)rows[tok] * F4_PER_ROW + col]);
    }

    // Streaming stores (write-once output, evict-first)
    float4* dst = out + (size_t)tok0 * F4_PER_ROW;
#pragma unroll
    for (int i = 0; i < ITERS; ++i)
        __stcs(dst + t + i * THREADS, v[i]);
}

extern "C" void kernel_launch(void* const* d_in, const int* in_sizes, int n_in,
                              void* d_out, int out_size)
{
    const int*    x   = (const int*)d_in[0];
    const float4* emb = (const float4*)d_in[1];
    float4*       out = (float4*)d_out;

    const int n_tokens = in_sizes[0];                 // 8192
    const int n_blocks = n_tokens / TOK_PER_BLK;      // 2048

    embedding_gather_kernel<<<n_blocks, THREADS>>>(x, emb, out);
}